// round 10
// baseline (speedup 1.0000x reference)
#include <cuda_runtime.h>
#include <math.h>

#define HW (1024 * 1024)
#define NPIX4 (HW / 4)          // 262144 float4 per plane
#define SBLK  512               // blocks for k_field (256 thr, 8 px/thread)
#define NGRAD_SM 258            // per-block gradients: sum 2*(RES+1)

// Scratch (allocation-free: __device__ globals)
__device__ float  g_bmn[5][SBLK];   // per-block partial minima (rewritten each run)
__device__ float  g_bmx[5][SBLK];   // per-block partial maxima
__device__ float4 g_noise4[NPIX4];  // final noise, pre-multiplied by mix

// grid barrier state: g_rel is MONOTONIC across graph replays (never reset)
__device__ unsigned int g_cnt = 0;
__device__ unsigned int g_rel = 0;

__device__ __forceinline__ void grid_barrier(unsigned target) {
    __syncthreads();
    if (threadIdx.x == 0) {
        __threadfence();                      // release this block's writes
        unsigned old = atomicAdd(&g_cnt, 1);
        if (old == gridDim.x - 1) {
            atomicExch(&g_cnt, 0);            // reset for next replay
            __threadfence();
            atomicAdd(&g_rel, 1);             // release everyone
        } else {
            while (*((volatile unsigned*)&g_rel) < target) { __nanosleep(32); }
        }
        __threadfence();                      // acquire
    }
    __syncthreads();
}

// ---------------------------------------------------------------------------
// Perlin per-cell-row constants.  For fixed row i and cell containing j0:
//   n(j) = t0 + wx*t1,  t0 = C0 + P1*D0,  t1 = E + P1*F
// (quartic in P1 — NOT monotone; min/max sampling below keeps 7-px spacing,
//  which measured 5.8e-7 output error vs exact)
// Gradients come from block-shared memory (2 rows x (RES+1) per octave).
// smem layout offsets (float2 units): O0:0  O1:10  O2:28  O3:62  O4:128
// ---------------------------------------------------------------------------
struct RunConst { float C0, D0, E, F; };

template <int O>
__device__ __forceinline__ RunConst run_const_sm(const float2* sg, int i, int j0) {
    constexpr int RES = 4 << O;
    constexpr int SH  = 8 - O;
    constexpr int SOFF[5] = {0, 10, 28, 62, 128};
    const float delta = (float)RES / 1023.0f;

    float vy = (float)i * delta;
    float P0 = vy - floorf(vy);
    float wy = P0 * P0 * (3.0f - 2.0f * P0);

    int cx = j0 >> SH;
    const float2* g = sg + SOFF[O];
    float2 g00 = g[cx];
    float2 g10 = g[(RES + 1) + cx];
    float2 g01 = g[cx + 1];
    float2 g11 = g[(RES + 1) + cx + 1];

    float A0 = P0 * g00.x;
    float A1 = (P0 - 1.0f) * g10.x;
    float B0 = P0 * g01.x - g01.y;
    float B1 = (P0 - 1.0f) * g11.x - g11.y;

    float C0 = A0 + wy * (A1 - A0);
    float D0 = g00.y + wy * (g10.y - g00.y);
    float C1 = B0 + wy * (B1 - B0);
    float D1 = g01.y + wy * (g11.y - g01.y);

    RunConst rc;
    rc.C0 = C0; rc.D0 = D0; rc.E = C1 - C0; rc.F = D1 - D0;
    return rc;
}

template <int O>
__device__ __forceinline__ float run_eval(const RunConst& rc, int j) {
    constexpr int RES = 4 << O;
    const float delta = (float)RES / 1023.0f;
    float vx = (float)j * delta;
    float P1 = vx - floorf(vx);
    float wx = P1 * P1 * (3.0f - 2.0f * P1);
    float t0 = fmaf(P1, rc.D0, rc.C0);
    float t1 = fmaf(P1, rc.F, rc.E);
    return fmaf(wx, t1, t0);
}

// ---------------------------------------------------------------------------
// Fill the block's gradient smem table: 2 rows x (RES+1) cos/sin per octave.
// Block covers rows i0, i0+1 (i0 even) -> one cell-row at every octave.
// Compile-time W per branch (mul-shift, no IDIV).  __sincosf: abs err ~5e-7.
// ---------------------------------------------------------------------------
#define FILL_BRANCH(o, BASE, W)                                         \
    {                                                                   \
        int local = idx - (BASE);                                       \
        int row = local / (W);                                          \
        int cx  = local - row * (W);                                    \
        int cy0 = i0 >> (8 - (o));                                      \
        float a = angs[o][(cy0 + row) * (W) + cx];                      \
        float s, c;                                                     \
        __sincosf(a, &s, &c);                                           \
        sg[idx] = make_float2(c, s);                                    \
    }

__device__ __forceinline__ void fill_grad_sm(
    float2* sg, int i0,
    const float* a0, const float* a1, const float* a2,
    const float* a3, const float* a4)
{
    const float* angs[5] = {a0, a1, a2, a3, a4};
#pragma unroll
    for (int rep = 0; rep < 2; rep++) {
        int idx = threadIdx.x + rep * 256;
        if      (idx < 10)       FILL_BRANCH(0, 0,   5)
        else if (idx < 28)       FILL_BRANCH(1, 10,  9)
        else if (idx < 62)       FILL_BRANCH(2, 28,  17)
        else if (idx < 128)      FILL_BRANCH(3, 62,  33)
        else if (idx < NGRAD_SM) FILL_BRANCH(4, 128, 65)
    }
}

// ---------------------------------------------------------------------------
// k_field: ONE kernel, two phases joined by a grid barrier.
//   Phase A: per-octave min/max partials sampled at run endpoints
//            (j0, j0+7 of every 8-px run; + j=1022 on the wrap run).
//            Shares the 5 RunConsts with phase B.
//   Phase B: reduce 512 block-partials, write normalized noise * mix.
//            One thread = one 8-px run; incremental P1/t-line evaluation.
// 512 blocks x 256 thr, <=64 regs (launch_bounds) => all blocks co-resident.
// ---------------------------------------------------------------------------
__global__ void __launch_bounds__(256, 4) k_field(
    const float* __restrict__ a0, const float* __restrict__ a1,
    const float* __restrict__ a2, const float* __restrict__ a3,
    const float* __restrict__ a4, const float* __restrict__ mixp)
{
    __shared__ float2 sgrad[NGRAD_SM];
    __shared__ float smn[5][8], smx[5][8];
    __shared__ float fmn[5], fmx[5];
    __shared__ unsigned s_r0;

    if (threadIdx.x == 0) s_r0 = *((volatile unsigned*)&g_rel);

    int i0 = blockIdx.x * 2;
    fill_grad_sm(sgrad, i0, a0, a1, a2, a3, a4);
    __syncthreads();           // covers sgrad AND s_r0
    unsigned R0 = s_r0;

    int t = blockIdx.x * 256 + threadIdx.x;   // 0..131071
    int i  = t >> 7;
    int j0 = (t & 127) << 3;
    bool wrap = (j0 == 1016);

    RunConst r0 = run_const_sm<0>(sgrad, i, j0);
    RunConst r1 = run_const_sm<1>(sgrad, i, j0);
    RunConst r2 = run_const_sm<2>(sgrad, i, j0);
    RunConst r3 = run_const_sm<3>(sgrad, i, j0);
    RunConst r4 = run_const_sm<4>(sgrad, i, j0);

    // ---- Phase A: run-endpoint min/max samples ----------------------------
    float mn[5], mx[5];
    {
        float a, b;
        a = run_eval<0>(r0, j0); b = run_eval<0>(r0, j0 + 7);
        mn[0] = fminf(a, b); mx[0] = fmaxf(a, b);
        a = run_eval<1>(r1, j0); b = run_eval<1>(r1, j0 + 7);
        mn[1] = fminf(a, b); mx[1] = fmaxf(a, b);
        a = run_eval<2>(r2, j0); b = run_eval<2>(r2, j0 + 7);
        mn[2] = fminf(a, b); mx[2] = fmaxf(a, b);
        a = run_eval<3>(r3, j0); b = run_eval<3>(r3, j0 + 7);
        mn[3] = fminf(a, b); mx[3] = fmaxf(a, b);
        a = run_eval<4>(r4, j0); b = run_eval<4>(r4, j0 + 7);
        mn[4] = fminf(a, b); mx[4] = fmaxf(a, b);
    }
    if (wrap) {   // P1 wraps to 0 at j=1023: also sample j=1022
        float c;
        c = run_eval<0>(r0, 1022); mn[0] = fminf(mn[0], c); mx[0] = fmaxf(mx[0], c);
        c = run_eval<1>(r1, 1022); mn[1] = fminf(mn[1], c); mx[1] = fmaxf(mx[1], c);
        c = run_eval<2>(r2, 1022); mn[2] = fminf(mn[2], c); mx[2] = fmaxf(mx[2], c);
        c = run_eval<3>(r3, 1022); mn[3] = fminf(mn[3], c); mx[3] = fmaxf(mx[3], c);
        c = run_eval<4>(r4, 1022); mn[4] = fminf(mn[4], c); mx[4] = fmaxf(mx[4], c);
    }

#pragma unroll
    for (int o = 0; o < 5; o++) {
#pragma unroll
        for (int d = 16; d > 0; d >>= 1) {
            mn[o] = fminf(mn[o], __shfl_xor_sync(0xFFFFFFFFu, mn[o], d));
            mx[o] = fmaxf(mx[o], __shfl_xor_sync(0xFFFFFFFFu, mx[o], d));
        }
    }
    int w = threadIdx.x >> 5, lane = threadIdx.x & 31;
    if (lane == 0) {
#pragma unroll
        for (int o = 0; o < 5; o++) { smn[o][w] = mn[o]; smx[o][w] = mx[o]; }
    }
    __syncthreads();
    if (threadIdx.x < 5) {
        int o = threadIdx.x;
        float a = smn[o][0], b = smx[o][0];
#pragma unroll
        for (int k = 1; k < 8; k++) { a = fminf(a, smn[o][k]); b = fmaxf(b, smx[o][k]); }
        g_bmn[o][blockIdx.x] = a;
        g_bmx[o][blockIdx.x] = b;
    }

    // ---- grid barrier: all partials visible -------------------------------
    grid_barrier(R0 + 1);

    // ---- Phase B: reduce partials (2 per thread, L2 loads) ----------------
    {
        float pm[5], px[5];
#pragma unroll
        for (int o = 0; o < 5; o++) {
            pm[o] = fminf(__ldcg(&g_bmn[o][threadIdx.x]),
                          __ldcg(&g_bmn[o][threadIdx.x + 256]));
            px[o] = fmaxf(__ldcg(&g_bmx[o][threadIdx.x]),
                          __ldcg(&g_bmx[o][threadIdx.x + 256]));
        }
#pragma unroll
        for (int o = 0; o < 5; o++) {
#pragma unroll
            for (int d = 16; d > 0; d >>= 1) {
                pm[o] = fminf(pm[o], __shfl_xor_sync(0xFFFFFFFFu, pm[o], d));
                px[o] = fmaxf(px[o], __shfl_xor_sync(0xFFFFFFFFu, px[o], d));
            }
        }
        if (lane == 0) {
#pragma unroll
            for (int o = 0; o < 5; o++) { smn[o][w] = pm[o]; smx[o][w] = px[o]; }
        }
    }
    __syncthreads();
    if (threadIdx.x < 5) {
        int o = threadIdx.x;
        float a = smn[o][0], b = smx[o][0];
#pragma unroll
        for (int k = 1; k < 8; k++) { a = fminf(a, smn[o][k]); b = fmaxf(b, smx[o][k]); }
        fmn[o] = a; fmx[o] = b;
    }
    __syncthreads();

    // fold normalization into per-octave scale + shared bias
    float mixv = *mixp;
    const float amps[5] = {0.1f, 0.05f, 0.025f, 0.0125f, 0.00625f};
    float s[5], B = 0.0f;
#pragma unroll
    for (int o = 0; o < 5; o++) {
        float mnv = fmn[o], mxv = fmx[o];
        float inv = 1.0f / (mxv - mnv);
        float am = amps[o] * mixv;
        s[o] = 2.0f * am * inv;
        B += am * (-2.0f * mnv * inv - 1.0f);
    }

    // ---- noise for this thread's 8-px run, incremental evaluation ---------
    const float dl[5] = {4.0f / 1023.0f, 8.0f / 1023.0f, 16.0f / 1023.0f,
                         32.0f / 1023.0f, 64.0f / 1023.0f};

    float P1[5], T1[5], dT1[5];
    float base = B, dbase = 0.0f;
#define INITO(o, rc)                                                    \
    {                                                                   \
        float vx = (float)j0 * dl[o];                                   \
        P1[o] = vx - floorf(vx);                                        \
        base  = fmaf(s[o], fmaf(P1[o], rc.D0, rc.C0), base);            \
        dbase = fmaf(s[o] * dl[o], rc.D0, dbase);                       \
        T1[o]  = s[o] * fmaf(P1[o], rc.F, rc.E);                        \
        dT1[o] = s[o] * dl[o] * rc.F;                                   \
    }
    INITO(0, r0) INITO(1, r1) INITO(2, r2) INITO(3, r3) INITO(4, r4)
#undef INITO

    float vals[8];
#pragma unroll
    for (int k = 0; k < 8; k++) {
        float acc = base;
#pragma unroll
        for (int o = 0; o < 5; o++) {
            float u = P1[o] * P1[o];
            float v = fmaf(-2.0f, P1[o], 3.0f);
            acc = fmaf(u * v, T1[o], acc);
        }
        vals[k] = acc;
#pragma unroll
        for (int o = 0; o < 5; o++) { P1[o] += dl[o]; T1[o] += dT1[o]; }
        base += dbase;
    }
    if (wrap) {   // j=1023: P1 wraps to 0 at every octave -> n_o = C0_o
        float acc = B;
        acc = fmaf(s[0], r0.C0, acc);
        acc = fmaf(s[1], r1.C0, acc);
        acc = fmaf(s[2], r2.C0, acc);
        acc = fmaf(s[3], r3.C0, acc);
        acc = fmaf(s[4], r4.C0, acc);
        vals[7] = acc;
    }

    int p4 = t << 1;
    g_noise4[p4]     = make_float4(vals[0], vals[1], vals[2], vals[3]);
    g_noise4[p4 + 1] = make_float4(vals[4], vals[5], vals[6], vals[7]);
}

// ---------------------------------------------------------------------------
// k_apply: HBM-bound streaming apply: out = clip(image + noise, 0, 1)
// VPT=6: 6 front-batched float4 loads/thread (MLP_p1=6), block-strided,
// streaming cache hints. n4 = 12582912 divides 1536 exactly.
// ---------------------------------------------------------------------------
#define VPT 6
__global__ void __launch_bounds__(256) k_apply(const float4* __restrict__ img,
                                               float4* __restrict__ out, int n4) {
    int base = blockIdx.x * (256 * VPT) + threadIdx.x;

    if (base + (VPT - 1) * 256 < n4) {
        float4 v[VPT], nz[VPT];
#pragma unroll
        for (int k = 0; k < VPT; k++) v[k] = __ldcs(img + base + k * 256);
#pragma unroll
        for (int k = 0; k < VPT; k++) nz[k] = g_noise4[(base + k * 256) & (NPIX4 - 1)];
#pragma unroll
        for (int k = 0; k < VPT; k++) {
            v[k].x = fminf(fmaxf(v[k].x + nz[k].x, 0.0f), 1.0f);
            v[k].y = fminf(fmaxf(v[k].y + nz[k].y, 0.0f), 1.0f);
            v[k].z = fminf(fmaxf(v[k].z + nz[k].z, 0.0f), 1.0f);
            v[k].w = fminf(fmaxf(v[k].w + nz[k].w, 0.0f), 1.0f);
        }
#pragma unroll
        for (int k = 0; k < VPT; k++) __stcs(out + base + k * 256, v[k]);
    } else {
        for (int k = 0; k < VPT; k++) {
            int idx = base + k * 256;
            if (idx >= n4) break;
            float4 nz = g_noise4[idx & (NPIX4 - 1)];
            float4 v = __ldcs(img + idx);
            v.x = fminf(fmaxf(v.x + nz.x, 0.0f), 1.0f);
            v.y = fminf(fmaxf(v.y + nz.y, 0.0f), 1.0f);
            v.z = fminf(fmaxf(v.z + nz.z, 0.0f), 1.0f);
            v.w = fminf(fmaxf(v.w + nz.w, 0.0f), 1.0f);
            __stcs(out + idx, v);
        }
    }
}

// ---------------------------------------------------------------------------
extern "C" void kernel_launch(void* const* d_in, const int* in_sizes, int n_in,
                              void* d_out, int out_size) {
    const float* image = nullptr;
    const float* mixp  = nullptr;
    const float* ang[5] = {nullptr, nullptr, nullptr, nullptr, nullptr};

    for (int k = 0; k < n_in; k++) {
        int s = in_sizes[k];
        const float* p = (const float*)d_in[k];
        if      (s == 1)    mixp   = p;
        else if (s == 25)   ang[0] = p;
        else if (s == 81)   ang[1] = p;
        else if (s == 289)  ang[2] = p;
        else if (s == 1089) ang[3] = p;
        else if (s == 4225) ang[4] = p;
        else                image  = p;   // 16*3*1024*1024
    }

    k_field<<<SBLK, 256>>>(ang[0], ang[1], ang[2], ang[3], ang[4], mixp);

    int n4 = out_size / 4;
    int blocks = (n4 + 256 * VPT - 1) / (256 * VPT);
    k_apply<<<blocks, 256>>>((const float4*)image, (float4*)d_out, n4);
}

// round 11
// speedup vs baseline: 1.0314x; 1.0314x over previous
#include <cuda_runtime.h>
#include <math.h>

#define HW (1024 * 1024)
#define NPIX4 (HW / 4)          // 262144 float4 per plane
#define SBLK  512               // blocks for k_field (256 thr, 8 px/thread)
#define NGRAD_SM 258            // per-block gradients: sum 2*(RES+1)

// Scratch (allocation-free: __device__ globals)
__device__ float  g_bmn[5][SBLK];   // per-block partial minima (rewritten each run)
__device__ float  g_bmx[5][SBLK];   // per-block partial maxima
__device__ float4 g_noise4[NPIX4];  // final noise, pre-multiplied by mix

// grid barrier state: g_rel is MONOTONIC across graph replays (never reset)
__device__ unsigned int g_cnt = 0;
__device__ unsigned int g_rel = 0;

__device__ __forceinline__ void grid_barrier(unsigned target) {
    __syncthreads();
    if (threadIdx.x == 0) {
        __threadfence();                      // release this block's writes
        unsigned old = atomicAdd(&g_cnt, 1);
        if (old == gridDim.x - 1) {
            atomicExch(&g_cnt, 0);            // reset for next replay
            __threadfence();
            atomicAdd(&g_rel, 1);             // release everyone
        } else {
            while (*((volatile unsigned*)&g_rel) < target) { __nanosleep(32); }
        }
        __threadfence();                      // acquire
    }
    __syncthreads();
}

// ---------------------------------------------------------------------------
// Perlin per-cell-row constants.  For fixed row i and cell containing j0:
//   n(j) = t0 + wx*t1,  t0 = C0 + P1*D0,  t1 = E + P1*F
// (quartic in P1 — NOT monotone; min/max sampling keeps 7-px spacing,
//  which measured 5.8e-7 output error vs exact)
// Gradients come from block-shared memory (2 rows x (RES+1) per octave).
// smem layout offsets (float2 units): O0:0  O1:10  O2:28  O3:62  O4:128
// ---------------------------------------------------------------------------
struct RunConst { float C0, D0, E, F; };

template <int O>
__device__ __forceinline__ RunConst run_const_sm(const float2* sg, int i, int j0) {
    constexpr int RES = 4 << O;
    constexpr int SH  = 8 - O;
    constexpr int SOFF[5] = {0, 10, 28, 62, 128};
    const float delta = (float)RES / 1023.0f;

    float vy = (float)i * delta;
    float P0 = vy - floorf(vy);
    float wy = P0 * P0 * (3.0f - 2.0f * P0);

    int cx = j0 >> SH;
    const float2* g = sg + SOFF[O];
    float2 g00 = g[cx];
    float2 g10 = g[(RES + 1) + cx];
    float2 g01 = g[cx + 1];
    float2 g11 = g[(RES + 1) + cx + 1];

    float A0 = P0 * g00.x;
    float A1 = (P0 - 1.0f) * g10.x;
    float B0 = P0 * g01.x - g01.y;
    float B1 = (P0 - 1.0f) * g11.x - g11.y;

    float C0 = A0 + wy * (A1 - A0);
    float D0 = g00.y + wy * (g10.y - g00.y);
    float C1 = B0 + wy * (B1 - B0);
    float D1 = g01.y + wy * (g11.y - g01.y);

    RunConst rc;
    rc.C0 = C0; rc.D0 = D0; rc.E = C1 - C0; rc.F = D1 - D0;
    return rc;
}

template <int O>
__device__ __forceinline__ float run_eval(const RunConst& rc, int j) {
    constexpr int RES = 4 << O;
    const float delta = (float)RES / 1023.0f;
    float vx = (float)j * delta;
    float P1 = vx - floorf(vx);
    float wx = P1 * P1 * (3.0f - 2.0f * P1);
    float t0 = fmaf(P1, rc.D0, rc.C0);
    float t1 = fmaf(P1, rc.F, rc.E);
    return fmaf(wx, t1, t0);
}

// ---------------------------------------------------------------------------
// Fill the block's gradient smem table: 2 rows x (RES+1) cos/sin per octave.
// Block covers rows i0, i0+1 (i0 even) -> one cell-row at every octave.
// Compile-time W per branch (mul-shift, no IDIV).  __sincosf: abs err ~5e-7.
// ---------------------------------------------------------------------------
#define FILL_BRANCH(o, BASE, W)                                         \
    {                                                                   \
        int local = idx - (BASE);                                       \
        int row = local / (W);                                          \
        int cx  = local - row * (W);                                    \
        int cy0 = i0 >> (8 - (o));                                      \
        float a = angs[o][(cy0 + row) * (W) + cx];                      \
        float s, c;                                                     \
        __sincosf(a, &s, &c);                                           \
        sg[idx] = make_float2(c, s);                                    \
    }

__device__ __forceinline__ void fill_grad_sm(
    float2* sg, int i0,
    const float* a0, const float* a1, const float* a2,
    const float* a3, const float* a4)
{
    const float* angs[5] = {a0, a1, a2, a3, a4};
#pragma unroll
    for (int rep = 0; rep < 2; rep++) {
        int idx = threadIdx.x + rep * 256;
        if      (idx < 10)       FILL_BRANCH(0, 0,   5)
        else if (idx < 28)       FILL_BRANCH(1, 10,  9)
        else if (idx < 62)       FILL_BRANCH(2, 28,  17)
        else if (idx < 128)      FILL_BRANCH(3, 62,  33)
        else if (idx < NGRAD_SM) FILL_BRANCH(4, 128, 65)
    }
}

// ---------------------------------------------------------------------------
// k_field: ONE kernel, two phases joined by a grid barrier.
//   Phase A: per-octave min/max partials sampled at run endpoints
//            (j0, j0+7 of every 8-px run; + j=1022 on the wrap run).
//   [PDL] after partials are written, release dependent launch (apply
//         blocks start prefetching image while we barrier + run phase B).
//   Phase B: reduce 512 block-partials, write normalized noise * mix.
//            One thread = one 8-px run; incremental P1/t-line evaluation.
// 512 blocks x 256 thr, <=64 regs (launch_bounds) => all blocks co-resident.
// ---------------------------------------------------------------------------
__global__ void __launch_bounds__(256, 4) k_field(
    const float* __restrict__ a0, const float* __restrict__ a1,
    const float* __restrict__ a2, const float* __restrict__ a3,
    const float* __restrict__ a4, const float* __restrict__ mixp)
{
    __shared__ float2 sgrad[NGRAD_SM];
    __shared__ float smn[5][8], smx[5][8];
    __shared__ float fmn[5], fmx[5];
    __shared__ unsigned s_r0;

    if (threadIdx.x == 0) s_r0 = *((volatile unsigned*)&g_rel);

    int i0 = blockIdx.x * 2;
    fill_grad_sm(sgrad, i0, a0, a1, a2, a3, a4);
    __syncthreads();           // covers sgrad AND s_r0
    unsigned R0 = s_r0;

    int t = blockIdx.x * 256 + threadIdx.x;   // 0..131071
    int i  = t >> 7;
    int j0 = (t & 127) << 3;
    bool wrap = (j0 == 1016);

    RunConst r0 = run_const_sm<0>(sgrad, i, j0);
    RunConst r1 = run_const_sm<1>(sgrad, i, j0);
    RunConst r2 = run_const_sm<2>(sgrad, i, j0);
    RunConst r3 = run_const_sm<3>(sgrad, i, j0);
    RunConst r4 = run_const_sm<4>(sgrad, i, j0);

    // ---- Phase A: run-endpoint min/max samples ----------------------------
    float mn[5], mx[5];
    {
        float a, b;
        a = run_eval<0>(r0, j0); b = run_eval<0>(r0, j0 + 7);
        mn[0] = fminf(a, b); mx[0] = fmaxf(a, b);
        a = run_eval<1>(r1, j0); b = run_eval<1>(r1, j0 + 7);
        mn[1] = fminf(a, b); mx[1] = fmaxf(a, b);
        a = run_eval<2>(r2, j0); b = run_eval<2>(r2, j0 + 7);
        mn[2] = fminf(a, b); mx[2] = fmaxf(a, b);
        a = run_eval<3>(r3, j0); b = run_eval<3>(r3, j0 + 7);
        mn[3] = fminf(a, b); mx[3] = fmaxf(a, b);
        a = run_eval<4>(r4, j0); b = run_eval<4>(r4, j0 + 7);
        mn[4] = fminf(a, b); mx[4] = fmaxf(a, b);
    }
    if (wrap) {   // P1 wraps to 0 at j=1023: also sample j=1022
        float c;
        c = run_eval<0>(r0, 1022); mn[0] = fminf(mn[0], c); mx[0] = fmaxf(mx[0], c);
        c = run_eval<1>(r1, 1022); mn[1] = fminf(mn[1], c); mx[1] = fmaxf(mx[1], c);
        c = run_eval<2>(r2, 1022); mn[2] = fminf(mn[2], c); mx[2] = fmaxf(mx[2], c);
        c = run_eval<3>(r3, 1022); mn[3] = fminf(mn[3], c); mx[3] = fmaxf(mx[3], c);
        c = run_eval<4>(r4, 1022); mn[4] = fminf(mn[4], c); mx[4] = fmaxf(mx[4], c);
    }

#pragma unroll
    for (int o = 0; o < 5; o++) {
#pragma unroll
        for (int d = 16; d > 0; d >>= 1) {
            mn[o] = fminf(mn[o], __shfl_xor_sync(0xFFFFFFFFu, mn[o], d));
            mx[o] = fmaxf(mx[o], __shfl_xor_sync(0xFFFFFFFFu, mx[o], d));
        }
    }
    int w = threadIdx.x >> 5, lane = threadIdx.x & 31;
    if (lane == 0) {
#pragma unroll
        for (int o = 0; o < 5; o++) { smn[o][w] = mn[o]; smx[o][w] = mx[o]; }
    }
    __syncthreads();
    if (threadIdx.x < 5) {
        int o = threadIdx.x;
        float a = smn[o][0], b = smx[o][0];
#pragma unroll
        for (int k = 1; k < 8; k++) { a = fminf(a, smn[o][k]); b = fmaxf(b, smx[o][k]); }
        g_bmn[o][blockIdx.x] = a;
        g_bmx[o][blockIdx.x] = b;
    }

    // ---- PDL: let k_apply blocks launch & prefetch image now --------------
    asm volatile("griddepcontrol.launch_dependents;");

    // ---- grid barrier: all partials visible -------------------------------
    grid_barrier(R0 + 1);

    // ---- Phase B: reduce partials (2 per thread, L2 loads) ----------------
    {
        float pm[5], px[5];
#pragma unroll
        for (int o = 0; o < 5; o++) {
            pm[o] = fminf(__ldcg(&g_bmn[o][threadIdx.x]),
                          __ldcg(&g_bmn[o][threadIdx.x + 256]));
            px[o] = fmaxf(__ldcg(&g_bmx[o][threadIdx.x]),
                          __ldcg(&g_bmx[o][threadIdx.x + 256]));
        }
#pragma unroll
        for (int o = 0; o < 5; o++) {
#pragma unroll
            for (int d = 16; d > 0; d >>= 1) {
                pm[o] = fminf(pm[o], __shfl_xor_sync(0xFFFFFFFFu, pm[o], d));
                px[o] = fmaxf(px[o], __shfl_xor_sync(0xFFFFFFFFu, px[o], d));
            }
        }
        if (lane == 0) {
#pragma unroll
            for (int o = 0; o < 5; o++) { smn[o][w] = pm[o]; smx[o][w] = px[o]; }
        }
    }
    __syncthreads();
    if (threadIdx.x < 5) {
        int o = threadIdx.x;
        float a = smn[o][0], b = smx[o][0];
#pragma unroll
        for (int k = 1; k < 8; k++) { a = fminf(a, smn[o][k]); b = fmaxf(b, smx[o][k]); }
        fmn[o] = a; fmx[o] = b;
    }
    __syncthreads();

    // fold normalization into per-octave scale + shared bias
    float mixv = *mixp;
    const float amps[5] = {0.1f, 0.05f, 0.025f, 0.0125f, 0.00625f};
    float s[5], B = 0.0f;
#pragma unroll
    for (int o = 0; o < 5; o++) {
        float mnv = fmn[o], mxv = fmx[o];
        float inv = 1.0f / (mxv - mnv);
        float am = amps[o] * mixv;
        s[o] = 2.0f * am * inv;
        B += am * (-2.0f * mnv * inv - 1.0f);
    }

    // ---- noise for this thread's 8-px run, incremental evaluation ---------
    const float dl[5] = {4.0f / 1023.0f, 8.0f / 1023.0f, 16.0f / 1023.0f,
                         32.0f / 1023.0f, 64.0f / 1023.0f};

    float P1[5], T1[5], dT1[5];
    float base = B, dbase = 0.0f;
#define INITO(o, rc)                                                    \
    {                                                                   \
        float vx = (float)j0 * dl[o];                                   \
        P1[o] = vx - floorf(vx);                                        \
        base  = fmaf(s[o], fmaf(P1[o], rc.D0, rc.C0), base);            \
        dbase = fmaf(s[o] * dl[o], rc.D0, dbase);                       \
        T1[o]  = s[o] * fmaf(P1[o], rc.F, rc.E);                        \
        dT1[o] = s[o] * dl[o] * rc.F;                                   \
    }
    INITO(0, r0) INITO(1, r1) INITO(2, r2) INITO(3, r3) INITO(4, r4)
#undef INITO

    float vals[8];
#pragma unroll
    for (int k = 0; k < 8; k++) {
        float acc = base;
#pragma unroll
        for (int o = 0; o < 5; o++) {
            float u = P1[o] * P1[o];
            float v = fmaf(-2.0f, P1[o], 3.0f);
            acc = fmaf(u * v, T1[o], acc);
        }
        vals[k] = acc;
#pragma unroll
        for (int o = 0; o < 5; o++) { P1[o] += dl[o]; T1[o] += dT1[o]; }
        base += dbase;
    }
    if (wrap) {   // j=1023: P1 wraps to 0 at every octave -> n_o = C0_o
        float acc = B;
        acc = fmaf(s[0], r0.C0, acc);
        acc = fmaf(s[1], r1.C0, acc);
        acc = fmaf(s[2], r2.C0, acc);
        acc = fmaf(s[3], r3.C0, acc);
        acc = fmaf(s[4], r4.C0, acc);
        vals[7] = acc;
    }

    int p4 = t << 1;
    g_noise4[p4]     = make_float4(vals[0], vals[1], vals[2], vals[3]);
    g_noise4[p4 + 1] = make_float4(vals[4], vals[5], vals[6], vals[7]);
}

// ---------------------------------------------------------------------------
// k_apply: HBM-bound streaming apply: out = clip(image + noise, 0, 1)
// Proven VPT=4 shape. PDL: img loads are issued BEFORE griddepcontrol.wait
// (independent of k_field); noise reads/stores after the wait.
// ---------------------------------------------------------------------------
#define VPT 4
__global__ void __launch_bounds__(256) k_apply(const float4* __restrict__ img,
                                               float4* __restrict__ out, int n4) {
    int base = blockIdx.x * (256 * VPT) + threadIdx.x;

    if (base + 3 * 256 < n4) {
        float4 v0 = __ldcs(img + base);
        float4 v1 = __ldcs(img + base + 256);
        float4 v2 = __ldcs(img + base + 512);
        float4 v3 = __ldcs(img + base + 768);

        asm volatile("griddepcontrol.wait;" ::: "memory");

        float4 n0 = g_noise4[(base)       & (NPIX4 - 1)];
        float4 n1 = g_noise4[(base + 256) & (NPIX4 - 1)];
        float4 n2 = g_noise4[(base + 512) & (NPIX4 - 1)];
        float4 n3 = g_noise4[(base + 768) & (NPIX4 - 1)];

        v0.x = fminf(fmaxf(v0.x + n0.x, 0.0f), 1.0f);
        v0.y = fminf(fmaxf(v0.y + n0.y, 0.0f), 1.0f);
        v0.z = fminf(fmaxf(v0.z + n0.z, 0.0f), 1.0f);
        v0.w = fminf(fmaxf(v0.w + n0.w, 0.0f), 1.0f);
        v1.x = fminf(fmaxf(v1.x + n1.x, 0.0f), 1.0f);
        v1.y = fminf(fmaxf(v1.y + n1.y, 0.0f), 1.0f);
        v1.z = fminf(fmaxf(v1.z + n1.z, 0.0f), 1.0f);
        v1.w = fminf(fmaxf(v1.w + n1.w, 0.0f), 1.0f);
        v2.x = fminf(fmaxf(v2.x + n2.x, 0.0f), 1.0f);
        v2.y = fminf(fmaxf(v2.y + n2.y, 0.0f), 1.0f);
        v2.z = fminf(fmaxf(v2.z + n2.z, 0.0f), 1.0f);
        v2.w = fminf(fmaxf(v2.w + n2.w, 0.0f), 1.0f);
        v3.x = fminf(fmaxf(v3.x + n3.x, 0.0f), 1.0f);
        v3.y = fminf(fmaxf(v3.y + n3.y, 0.0f), 1.0f);
        v3.z = fminf(fmaxf(v3.z + n3.z, 0.0f), 1.0f);
        v3.w = fminf(fmaxf(v3.w + n3.w, 0.0f), 1.0f);

        __stcs(out + base,       v0);
        __stcs(out + base + 256, v1);
        __stcs(out + base + 512, v2);
        __stcs(out + base + 768, v3);
    } else {
        asm volatile("griddepcontrol.wait;" ::: "memory");
        for (int k = 0; k < VPT; k++) {
            int idx = base + k * 256;
            if (idx >= n4) break;
            float4 nz = g_noise4[idx & (NPIX4 - 1)];
            float4 v = __ldcs(img + idx);
            v.x = fminf(fmaxf(v.x + nz.x, 0.0f), 1.0f);
            v.y = fminf(fmaxf(v.y + nz.y, 0.0f), 1.0f);
            v.z = fminf(fmaxf(v.z + nz.z, 0.0f), 1.0f);
            v.w = fminf(fmaxf(v.w + nz.w, 0.0f), 1.0f);
            __stcs(out + idx, v);
        }
    }
}

// ---------------------------------------------------------------------------
extern "C" void kernel_launch(void* const* d_in, const int* in_sizes, int n_in,
                              void* d_out, int out_size) {
    const float* image = nullptr;
    const float* mixp  = nullptr;
    const float* ang[5] = {nullptr, nullptr, nullptr, nullptr, nullptr};

    for (int k = 0; k < n_in; k++) {
        int s = in_sizes[k];
        const float* p = (const float*)d_in[k];
        if      (s == 1)    mixp   = p;
        else if (s == 25)   ang[0] = p;
        else if (s == 81)   ang[1] = p;
        else if (s == 289)  ang[2] = p;
        else if (s == 1089) ang[3] = p;
        else if (s == 4225) ang[4] = p;
        else                image  = p;   // 16*3*1024*1024
    }

    k_field<<<SBLK, 256>>>(ang[0], ang[1], ang[2], ang[3], ang[4], mixp);

    int n4 = out_size / 4;
    unsigned blocks = (unsigned)((n4 + 256 * VPT - 1) / (256 * VPT));

    // PDL launch: k_apply may begin (and prefetch image) while k_field runs;
    // griddepcontrol.wait inside k_apply gates the dependent noise reads.
    cudaLaunchConfig_t cfg = {};
    cfg.gridDim  = dim3(blocks, 1, 1);
    cfg.blockDim = dim3(256, 1, 1);
    cfg.dynamicSmemBytes = 0;
    cudaLaunchAttribute attrs[1];
    attrs[0].id = cudaLaunchAttributeProgrammaticStreamSerialization;
    attrs[0].val.programmaticStreamSerializationAllowed = 1;
    cfg.attrs = attrs;
    cfg.numAttrs = 1;
    cudaError_t e = cudaLaunchKernelEx(&cfg, k_apply,
                                       (const float4*)image, (float4*)d_out, n4);
    if (e != cudaSuccess) {
        // fallback: plain launch (griddepcontrol.wait degenerates to no-op)
        k_apply<<<blocks, 256>>>((const float4*)image, (float4*)d_out, n4);
    }
}

// round 12
// speedup vs baseline: 1.0413x; 1.0096x over previous
#include <cuda_runtime.h>
#include <math.h>

#define HW (1024 * 1024)
#define NPIX4 (HW / 4)          // 262144 float4 per plane
#define SBLK  512               // blocks for k_minmax/k_noise (256 thr, 8 px/thread)
#define NGRAD_SM 258            // per-block gradients: sum 2*(RES+1)

// Scratch (allocation-free: __device__ globals)
__device__ float  g_bmn[5][SBLK];   // per-block partial minima (rewritten each run)
__device__ float  g_bmx[5][SBLK];   // per-block partial maxima
__device__ float4 g_noise4[NPIX4];  // final noise, pre-multiplied by mix

// ---------------------------------------------------------------------------
// Perlin per-cell-row constants.  For fixed row i and cell containing j0:
//   n(j) = t0 + wx*t1,  t0 = C0 + P1*D0,  t1 = E + P1*F
// (quartic in P1 — NOT monotone; min/max sampling keeps 7-px spacing,
//  which measured 5.8e-7 output error vs exact)
// Gradients come from block-shared memory (2 rows x (RES+1) per octave).
// smem layout offsets (float2 units): O0:0  O1:10  O2:28  O3:62  O4:128
// ---------------------------------------------------------------------------
struct RunConst { float C0, D0, E, F; };

template <int O>
__device__ __forceinline__ RunConst run_const_sm(const float2* sg, int i, int j0) {
    constexpr int RES = 4 << O;
    constexpr int SH  = 8 - O;
    constexpr int SOFF[5] = {0, 10, 28, 62, 128};
    const float delta = (float)RES / 1023.0f;

    float vy = (float)i * delta;
    float P0 = vy - floorf(vy);
    float wy = P0 * P0 * (3.0f - 2.0f * P0);

    int cx = j0 >> SH;
    const float2* g = sg + SOFF[O];
    float2 g00 = g[cx];
    float2 g10 = g[(RES + 1) + cx];
    float2 g01 = g[cx + 1];
    float2 g11 = g[(RES + 1) + cx + 1];

    float A0 = P0 * g00.x;
    float A1 = (P0 - 1.0f) * g10.x;
    float B0 = P0 * g01.x - g01.y;
    float B1 = (P0 - 1.0f) * g11.x - g11.y;

    float C0 = A0 + wy * (A1 - A0);
    float D0 = g00.y + wy * (g10.y - g00.y);
    float C1 = B0 + wy * (B1 - B0);
    float D1 = g01.y + wy * (g11.y - g01.y);

    RunConst rc;
    rc.C0 = C0; rc.D0 = D0; rc.E = C1 - C0; rc.F = D1 - D0;
    return rc;
}

template <int O>
__device__ __forceinline__ float run_eval(const RunConst& rc, int j) {
    constexpr int RES = 4 << O;
    const float delta = (float)RES / 1023.0f;
    float vx = (float)j * delta;
    float P1 = vx - floorf(vx);
    float wx = P1 * P1 * (3.0f - 2.0f * P1);
    float t0 = fmaf(P1, rc.D0, rc.C0);
    float t1 = fmaf(P1, rc.F, rc.E);
    return fmaf(wx, t1, t0);
}

// ---------------------------------------------------------------------------
// Fill the block's gradient smem table: 2 rows x (RES+1) cos/sin per octave.
// Block covers rows i0, i0+1 (i0 even) -> one cell-row at every octave.
// Compile-time W per branch (mul-shift, no IDIV).  __sincosf: abs err ~5e-7.
// ---------------------------------------------------------------------------
#define FILL_BRANCH(o, BASE, W)                                         \
    {                                                                   \
        int local = idx - (BASE);                                       \
        int row = local / (W);                                          \
        int cx  = local - row * (W);                                    \
        int cy0 = i0 >> (8 - (o));                                      \
        float a = angs[o][(cy0 + row) * (W) + cx];                      \
        float s, c;                                                     \
        __sincosf(a, &s, &c);                                           \
        sg[idx] = make_float2(c, s);                                    \
    }

__device__ __forceinline__ void fill_grad_sm(
    float2* sg, int i0,
    const float* a0, const float* a1, const float* a2,
    const float* a3, const float* a4)
{
    const float* angs[5] = {a0, a1, a2, a3, a4};
#pragma unroll
    for (int rep = 0; rep < 2; rep++) {
        int idx = threadIdx.x + rep * 256;
        if      (idx < 10)       FILL_BRANCH(0, 0,   5)
        else if (idx < 28)       FILL_BRANCH(1, 10,  9)
        else if (idx < 62)       FILL_BRANCH(2, 28,  17)
        else if (idx < 128)      FILL_BRANCH(3, 62,  33)
        else if (idx < NGRAD_SM) FILL_BRANCH(4, 128, 65)
    }
}

// ---------------------------------------------------------------------------
// K1 k_minmax: per-octave min/max partials sampled at run endpoints
// (j0, j0+7 of every 8-px run; + j=1022 on the wrap run).
// launch_dependents at entry: k_noise gets resident and runs its prologue
// (fill + run_consts) concurrently; its griddepcontrol.wait still gates on
// this grid's FULL completion, so partials are visible.
// ---------------------------------------------------------------------------
__global__ void __launch_bounds__(256) k_minmax(
    const float* __restrict__ a0, const float* __restrict__ a1,
    const float* __restrict__ a2, const float* __restrict__ a3,
    const float* __restrict__ a4)
{
    asm volatile("griddepcontrol.launch_dependents;");

    __shared__ float2 sgrad[NGRAD_SM];
    int i0 = blockIdx.x * 2;
    fill_grad_sm(sgrad, i0, a0, a1, a2, a3, a4);
    __syncthreads();

    int t = blockIdx.x * 256 + threadIdx.x;   // 0..131071
    int i  = t >> 7;
    int j0 = (t & 127) << 3;
    bool wrap = (j0 == 1016);

    RunConst r0 = run_const_sm<0>(sgrad, i, j0);
    RunConst r1 = run_const_sm<1>(sgrad, i, j0);
    RunConst r2 = run_const_sm<2>(sgrad, i, j0);
    RunConst r3 = run_const_sm<3>(sgrad, i, j0);
    RunConst r4 = run_const_sm<4>(sgrad, i, j0);

    float mn[5], mx[5];
    {
        float a, b;
        a = run_eval<0>(r0, j0); b = run_eval<0>(r0, j0 + 7);
        mn[0] = fminf(a, b); mx[0] = fmaxf(a, b);
        a = run_eval<1>(r1, j0); b = run_eval<1>(r1, j0 + 7);
        mn[1] = fminf(a, b); mx[1] = fmaxf(a, b);
        a = run_eval<2>(r2, j0); b = run_eval<2>(r2, j0 + 7);
        mn[2] = fminf(a, b); mx[2] = fmaxf(a, b);
        a = run_eval<3>(r3, j0); b = run_eval<3>(r3, j0 + 7);
        mn[3] = fminf(a, b); mx[3] = fmaxf(a, b);
        a = run_eval<4>(r4, j0); b = run_eval<4>(r4, j0 + 7);
        mn[4] = fminf(a, b); mx[4] = fmaxf(a, b);
    }
    if (wrap) {   // P1 wraps to 0 at j=1023: also sample j=1022
        float c;
        c = run_eval<0>(r0, 1022); mn[0] = fminf(mn[0], c); mx[0] = fmaxf(mx[0], c);
        c = run_eval<1>(r1, 1022); mn[1] = fminf(mn[1], c); mx[1] = fmaxf(mx[1], c);
        c = run_eval<2>(r2, 1022); mn[2] = fminf(mn[2], c); mx[2] = fmaxf(mx[2], c);
        c = run_eval<3>(r3, 1022); mn[3] = fminf(mn[3], c); mx[3] = fmaxf(mx[3], c);
        c = run_eval<4>(r4, 1022); mn[4] = fminf(mn[4], c); mx[4] = fmaxf(mx[4], c);
    }

#pragma unroll
    for (int o = 0; o < 5; o++) {
#pragma unroll
        for (int d = 16; d > 0; d >>= 1) {
            mn[o] = fminf(mn[o], __shfl_xor_sync(0xFFFFFFFFu, mn[o], d));
            mx[o] = fmaxf(mx[o], __shfl_xor_sync(0xFFFFFFFFu, mx[o], d));
        }
    }
    __shared__ float smn[5][8], smx[5][8];
    int w = threadIdx.x >> 5, lane = threadIdx.x & 31;
    if (lane == 0) {
#pragma unroll
        for (int o = 0; o < 5; o++) { smn[o][w] = mn[o]; smx[o][w] = mx[o]; }
    }
    __syncthreads();
    if (threadIdx.x < 5) {
        int o = threadIdx.x;
        float a = smn[o][0], b = smx[o][0];
#pragma unroll
        for (int k = 1; k < 8; k++) { a = fminf(a, smn[o][k]); b = fmaxf(b, smx[o][k]); }
        g_bmn[o][blockIdx.x] = a;
        g_bmx[o][blockIdx.x] = b;
    }
}

// ---------------------------------------------------------------------------
// K2 k_noise (PDL-dependent on k_minmax): prologue (fill + run_consts +
// unscaled incremental init) runs BEFORE the wait, overlapping k_minmax.
// After wait: reduce 512 partials, fold normalization, write noise * mix.
// launch_dependents at entry lets k_apply start prefetching image.
// ---------------------------------------------------------------------------
__global__ void __launch_bounds__(256) k_noise(
    const float* __restrict__ a0, const float* __restrict__ a1,
    const float* __restrict__ a2, const float* __restrict__ a3,
    const float* __restrict__ a4, const float* __restrict__ mixp)
{
    asm volatile("griddepcontrol.launch_dependents;");

    __shared__ float2 sgrad[NGRAD_SM];
    __shared__ float smn[5][8], smx[5][8];
    __shared__ float fmn[5], fmx[5];

    int i0 = blockIdx.x * 2;
    fill_grad_sm(sgrad, i0, a0, a1, a2, a3, a4);
    __syncthreads();

    int t = blockIdx.x * 256 + threadIdx.x;   // 0..131071
    int i  = t >> 7;
    int j0 = (t & 127) << 3;
    bool wrap = (j0 == 1016);

    RunConst r0 = run_const_sm<0>(sgrad, i, j0);
    RunConst r1 = run_const_sm<1>(sgrad, i, j0);
    RunConst r2 = run_const_sm<2>(sgrad, i, j0);
    RunConst r3 = run_const_sm<3>(sgrad, i, j0);
    RunConst r4 = run_const_sm<4>(sgrad, i, j0);

    // unscaled incremental state (independent of min/max):
    //   t0_o(j) = C0 + P1*D0;  T1u_o(j) = E + P1*F;  step by dl per pixel
    const float dl[5] = {4.0f / 1023.0f, 8.0f / 1023.0f, 16.0f / 1023.0f,
                         32.0f / 1023.0f, 64.0f / 1023.0f};
    float P1[5], t0[5], dt0[5], T1u[5], dT1u[5];
#define INITO(o, rc)                                                    \
    {                                                                   \
        float vx = (float)j0 * dl[o];                                   \
        P1[o]   = vx - floorf(vx);                                      \
        t0[o]   = fmaf(P1[o], rc.D0, rc.C0);                            \
        dt0[o]  = dl[o] * rc.D0;                                        \
        T1u[o]  = fmaf(P1[o], rc.F, rc.E);                              \
        dT1u[o] = dl[o] * rc.F;                                         \
    }
    INITO(0, r0) INITO(1, r1) INITO(2, r2) INITO(3, r3) INITO(4, r4)
#undef INITO

    // ---- wait for k_minmax grid to fully complete --------------------------
    asm volatile("griddepcontrol.wait;" ::: "memory");

    // reduce the 512 partials (2 per thread, L2 loads)
    int w = threadIdx.x >> 5, lane = threadIdx.x & 31;
    {
        float pm[5], px[5];
#pragma unroll
        for (int o = 0; o < 5; o++) {
            pm[o] = fminf(__ldcg(&g_bmn[o][threadIdx.x]),
                          __ldcg(&g_bmn[o][threadIdx.x + 256]));
            px[o] = fmaxf(__ldcg(&g_bmx[o][threadIdx.x]),
                          __ldcg(&g_bmx[o][threadIdx.x + 256]));
        }
#pragma unroll
        for (int o = 0; o < 5; o++) {
#pragma unroll
            for (int d = 16; d > 0; d >>= 1) {
                pm[o] = fminf(pm[o], __shfl_xor_sync(0xFFFFFFFFu, pm[o], d));
                px[o] = fmaxf(px[o], __shfl_xor_sync(0xFFFFFFFFu, px[o], d));
            }
        }
        if (lane == 0) {
#pragma unroll
            for (int o = 0; o < 5; o++) { smn[o][w] = pm[o]; smx[o][w] = px[o]; }
        }
    }
    __syncthreads();
    if (threadIdx.x < 5) {
        int o = threadIdx.x;
        float a = smn[o][0], b = smx[o][0];
#pragma unroll
        for (int k = 1; k < 8; k++) { a = fminf(a, smn[o][k]); b = fmaxf(b, smx[o][k]); }
        fmn[o] = a; fmx[o] = b;
    }
    __syncthreads();

    // fold normalization into per-octave scale + shared bias
    float mixv = *mixp;
    const float amps[5] = {0.1f, 0.05f, 0.025f, 0.0125f, 0.00625f};
    float s[5], B = 0.0f;
#pragma unroll
    for (int o = 0; o < 5; o++) {
        float mnv = fmn[o], mxv = fmx[o];
        float inv = 1.0f / (mxv - mnv);
        float am = amps[o] * mixv;
        s[o] = 2.0f * am * inv;
        B += am * (-2.0f * mnv * inv - 1.0f);
    }

    float vals[8];
#pragma unroll
    for (int k = 0; k < 8; k++) {
        float acc = B;
#pragma unroll
        for (int o = 0; o < 5; o++) {
            float u = P1[o] * P1[o];
            float v = fmaf(-2.0f, P1[o], 3.0f);
            acc = fmaf(s[o], fmaf(u * v, T1u[o], t0[o]), acc);
        }
        vals[k] = acc;
#pragma unroll
        for (int o = 0; o < 5; o++) {
            P1[o] += dl[o]; t0[o] += dt0[o]; T1u[o] += dT1u[o];
        }
    }
    if (wrap) {   // j=1023: P1 wraps to 0 at every octave -> n_o = C0_o
        float acc = B;
        acc = fmaf(s[0], r0.C0, acc);
        acc = fmaf(s[1], r1.C0, acc);
        acc = fmaf(s[2], r2.C0, acc);
        acc = fmaf(s[3], r3.C0, acc);
        acc = fmaf(s[4], r4.C0, acc);
        vals[7] = acc;
    }

    int p4 = t << 1;
    g_noise4[p4]     = make_float4(vals[0], vals[1], vals[2], vals[3]);
    g_noise4[p4 + 1] = make_float4(vals[4], vals[5], vals[6], vals[7]);
}

// ---------------------------------------------------------------------------
// K3 k_apply (PDL-dependent on k_noise): HBM-bound streaming apply.
// Proven VPT=4 shape: img loads issued BEFORE griddepcontrol.wait;
// noise reads/stores after the wait.
// ---------------------------------------------------------------------------
#define VPT 4
__global__ void __launch_bounds__(256) k_apply(const float4* __restrict__ img,
                                               float4* __restrict__ out, int n4) {
    int base = blockIdx.x * (256 * VPT) + threadIdx.x;

    if (base + 3 * 256 < n4) {
        float4 v0 = __ldcs(img + base);
        float4 v1 = __ldcs(img + base + 256);
        float4 v2 = __ldcs(img + base + 512);
        float4 v3 = __ldcs(img + base + 768);

        asm volatile("griddepcontrol.wait;" ::: "memory");

        float4 n0 = g_noise4[(base)       & (NPIX4 - 1)];
        float4 n1 = g_noise4[(base + 256) & (NPIX4 - 1)];
        float4 n2 = g_noise4[(base + 512) & (NPIX4 - 1)];
        float4 n3 = g_noise4[(base + 768) & (NPIX4 - 1)];

        v0.x = fminf(fmaxf(v0.x + n0.x, 0.0f), 1.0f);
        v0.y = fminf(fmaxf(v0.y + n0.y, 0.0f), 1.0f);
        v0.z = fminf(fmaxf(v0.z + n0.z, 0.0f), 1.0f);
        v0.w = fminf(fmaxf(v0.w + n0.w, 0.0f), 1.0f);
        v1.x = fminf(fmaxf(v1.x + n1.x, 0.0f), 1.0f);
        v1.y = fminf(fmaxf(v1.y + n1.y, 0.0f), 1.0f);
        v1.z = fminf(fmaxf(v1.z + n1.z, 0.0f), 1.0f);
        v1.w = fminf(fmaxf(v1.w + n1.w, 0.0f), 1.0f);
        v2.x = fminf(fmaxf(v2.x + n2.x, 0.0f), 1.0f);
        v2.y = fminf(fmaxf(v2.y + n2.y, 0.0f), 1.0f);
        v2.z = fminf(fmaxf(v2.z + n2.z, 0.0f), 1.0f);
        v2.w = fminf(fmaxf(v2.w + n2.w, 0.0f), 1.0f);
        v3.x = fminf(fmaxf(v3.x + n3.x, 0.0f), 1.0f);
        v3.y = fminf(fmaxf(v3.y + n3.y, 0.0f), 1.0f);
        v3.z = fminf(fmaxf(v3.z + n3.z, 0.0f), 1.0f);
        v3.w = fminf(fmaxf(v3.w + n3.w, 0.0f), 1.0f);

        __stcs(out + base,       v0);
        __stcs(out + base + 256, v1);
        __stcs(out + base + 512, v2);
        __stcs(out + base + 768, v3);
    } else {
        asm volatile("griddepcontrol.wait;" ::: "memory");
        for (int k = 0; k < VPT; k++) {
            int idx = base + k * 256;
            if (idx >= n4) break;
            float4 nz = g_noise4[idx & (NPIX4 - 1)];
            float4 v = __ldcs(img + idx);
            v.x = fminf(fmaxf(v.x + nz.x, 0.0f), 1.0f);
            v.y = fminf(fmaxf(v.y + nz.y, 0.0f), 1.0f);
            v.z = fminf(fmaxf(v.z + nz.z, 0.0f), 1.0f);
            v.w = fminf(fmaxf(v.w + nz.w, 0.0f), 1.0f);
            __stcs(out + idx, v);
        }
    }
}

// ---------------------------------------------------------------------------
extern "C" void kernel_launch(void* const* d_in, const int* in_sizes, int n_in,
                              void* d_out, int out_size) {
    const float* image = nullptr;
    const float* mixp  = nullptr;
    const float* ang[5] = {nullptr, nullptr, nullptr, nullptr, nullptr};

    for (int k = 0; k < n_in; k++) {
        int s = in_sizes[k];
        const float* p = (const float*)d_in[k];
        if      (s == 1)    mixp   = p;
        else if (s == 25)   ang[0] = p;
        else if (s == 81)   ang[1] = p;
        else if (s == 289)  ang[2] = p;
        else if (s == 1089) ang[3] = p;
        else if (s == 4225) ang[4] = p;
        else                image  = p;   // 16*3*1024*1024
    }

    int n4 = out_size / 4;
    unsigned ablocks = (unsigned)((n4 + 256 * VPT - 1) / (256 * VPT));

    // K1: plain launch
    k_minmax<<<SBLK, 256>>>(ang[0], ang[1], ang[2], ang[3], ang[4]);

    // K2: PDL-dependent launch (prologue overlaps k_minmax)
    cudaLaunchAttribute attrs[1];
    attrs[0].id = cudaLaunchAttributeProgrammaticStreamSerialization;
    attrs[0].val.programmaticStreamSerializationAllowed = 1;

    cudaLaunchConfig_t cfg2 = {};
    cfg2.gridDim  = dim3(SBLK, 1, 1);
    cfg2.blockDim = dim3(256, 1, 1);
    cfg2.attrs = attrs;
    cfg2.numAttrs = 1;
    cudaError_t e2 = cudaLaunchKernelEx(&cfg2, k_noise,
                                        ang[0], ang[1], ang[2], ang[3], ang[4], mixp);
    if (e2 != cudaSuccess) {
        k_noise<<<SBLK, 256>>>(ang[0], ang[1], ang[2], ang[3], ang[4], mixp);
    }

    // K3: PDL-dependent launch (img prefetch overlaps k_noise)
    cudaLaunchConfig_t cfg3 = {};
    cfg3.gridDim  = dim3(ablocks, 1, 1);
    cfg3.blockDim = dim3(256, 1, 1);
    cfg3.attrs = attrs;
    cfg3.numAttrs = 1;
    cudaError_t e3 = cudaLaunchKernelEx(&cfg3, k_apply,
                                        (const float4*)image, (float4*)d_out, n4);
    if (e3 != cudaSuccess) {
        k_apply<<<ablocks, 256>>>((const float4*)image, (float4*)d_out, n4);
    }
}

// round 13
// speedup vs baseline: 1.0583x; 1.0163x over previous
#include <cuda_runtime.h>
#include <math.h>

#define HW (1024 * 1024)
#define NPIX4 (HW / 4)          // 262144 float4 per plane
#define SBLK  512               // blocks for k_noise (256 thr, 8 px/thread)
#define MNBLK 128               // blocks for k_minmax (256 thr, 32-px window/thread)
#define NGRAD_SM 258            // per-block gradients: sum 2*(RES+1)

// Scratch (allocation-free: __device__ globals)
__device__ float  g_bmn[5][MNBLK];  // per-block partial minima (rewritten each run)
__device__ float  g_bmx[5][MNBLK];  // per-block partial maxima
__device__ float4 g_noise4[NPIX4];  // final noise, pre-multiplied by mix

// ---------------------------------------------------------------------------
// Perlin per-cell-row constants.  For fixed row i and cell containing j0:
//   n(j) = t0 + wx*t1,  t0 = C0 + P1*D0,  t1 = E + P1*F
// (quartic in P1 — NOT monotone; min/max sampling uses 31-px column spacing,
//  rows dense: predicted ~1e-5 output error, 100x under the 1e-3 threshold)
// Gradients come from block-shared memory (2 rows x (RES+1) per octave).
// smem layout offsets (float2 units): O0:0  O1:10  O2:28  O3:62  O4:128
// ---------------------------------------------------------------------------
struct RunConst { float C0, D0, E, F; };

template <int O>
__device__ __forceinline__ RunConst run_const_sm(const float2* sg, int i, int j0) {
    constexpr int RES = 4 << O;
    constexpr int SH  = 8 - O;
    constexpr int SOFF[5] = {0, 10, 28, 62, 128};
    const float delta = (float)RES / 1023.0f;

    float vy = (float)i * delta;
    float P0 = vy - floorf(vy);
    float wy = P0 * P0 * (3.0f - 2.0f * P0);

    int cx = j0 >> SH;
    const float2* g = sg + SOFF[O];
    float2 g00 = g[cx];
    float2 g10 = g[(RES + 1) + cx];
    float2 g01 = g[cx + 1];
    float2 g11 = g[(RES + 1) + cx + 1];

    float A0 = P0 * g00.x;
    float A1 = (P0 - 1.0f) * g10.x;
    float B0 = P0 * g01.x - g01.y;
    float B1 = (P0 - 1.0f) * g11.x - g11.y;

    float C0 = A0 + wy * (A1 - A0);
    float D0 = g00.y + wy * (g10.y - g00.y);
    float C1 = B0 + wy * (B1 - B0);
    float D1 = g01.y + wy * (g11.y - g01.y);

    RunConst rc;
    rc.C0 = C0; rc.D0 = D0; rc.E = C1 - C0; rc.F = D1 - D0;
    return rc;
}

template <int O>
__device__ __forceinline__ float run_eval(const RunConst& rc, int j) {
    constexpr int RES = 4 << O;
    const float delta = (float)RES / 1023.0f;
    float vx = (float)j * delta;
    float P1 = vx - floorf(vx);
    float wx = P1 * P1 * (3.0f - 2.0f * P1);
    float t0 = fmaf(P1, rc.D0, rc.C0);
    float t1 = fmaf(P1, rc.F, rc.E);
    return fmaf(wx, t1, t0);
}

// ---------------------------------------------------------------------------
// Fill the block's gradient smem table: 2 rows x (RES+1) cos/sin per octave.
// Valid when the block's rows [i0, i0+nrows) lie in ONE cell-row at every
// octave (cell height >= 16; nrows<=8 with i0 8-aligned, or 2 with i0 even).
// Compile-time W per branch (mul-shift, no IDIV).  __sincosf: abs err ~5e-7.
// ---------------------------------------------------------------------------
#define FILL_BRANCH(o, BASE, W)                                         \
    {                                                                   \
        int local = idx - (BASE);                                       \
        int row = local / (W);                                          \
        int cx  = local - row * (W);                                    \
        int cy0 = i0 >> (8 - (o));                                      \
        float a = angs[o][(cy0 + row) * (W) + cx];                      \
        float s, c;                                                     \
        __sincosf(a, &s, &c);                                           \
        sg[idx] = make_float2(c, s);                                    \
    }

__device__ __forceinline__ void fill_grad_sm(
    float2* sg, int i0,
    const float* a0, const float* a1, const float* a2,
    const float* a3, const float* a4)
{
    const float* angs[5] = {a0, a1, a2, a3, a4};
#pragma unroll
    for (int rep = 0; rep < 2; rep++) {
        int idx = threadIdx.x + rep * 256;
        if      (idx < 10)       FILL_BRANCH(0, 0,   5)
        else if (idx < 28)       FILL_BRANCH(1, 10,  9)
        else if (idx < 62)       FILL_BRANCH(2, 28,  17)
        else if (idx < 128)      FILL_BRANCH(3, 62,  33)
        else if (idx < NGRAD_SM) FILL_BRANCH(4, 128, 65)
    }
}

// ---------------------------------------------------------------------------
// K1 k_minmax: per-octave min/max partials.  One thread = one 32-px window
// (evals at j0 and j0+31; + j=1022 on the last window where P1 wraps).
// Block covers 8 rows (8-aligned => one cell-row at every octave).
// 128 blocks x 256 threads.  launch_dependents at entry (PDL).
// ---------------------------------------------------------------------------
__global__ void __launch_bounds__(256) k_minmax(
    const float* __restrict__ a0, const float* __restrict__ a1,
    const float* __restrict__ a2, const float* __restrict__ a3,
    const float* __restrict__ a4)
{
    asm volatile("griddepcontrol.launch_dependents;");

    __shared__ float2 sgrad[NGRAD_SM];
    int i0 = blockIdx.x * 8;
    fill_grad_sm(sgrad, i0, a0, a1, a2, a3, a4);
    __syncthreads();

    int i  = i0 + (threadIdx.x >> 5);      // 8 rows per block
    int j0 = (threadIdx.x & 31) << 5;      // 32 windows per row
    bool wrap = (j0 == 992);

    RunConst r0 = run_const_sm<0>(sgrad, i, j0);
    RunConst r1 = run_const_sm<1>(sgrad, i, j0);
    RunConst r2 = run_const_sm<2>(sgrad, i, j0);
    RunConst r3 = run_const_sm<3>(sgrad, i, j0);
    RunConst r4 = run_const_sm<4>(sgrad, i, j0);

    float mn[5], mx[5];
    {
        float a, b;
        a = run_eval<0>(r0, j0); b = run_eval<0>(r0, j0 + 31);
        mn[0] = fminf(a, b); mx[0] = fmaxf(a, b);
        a = run_eval<1>(r1, j0); b = run_eval<1>(r1, j0 + 31);
        mn[1] = fminf(a, b); mx[1] = fmaxf(a, b);
        a = run_eval<2>(r2, j0); b = run_eval<2>(r2, j0 + 31);
        mn[2] = fminf(a, b); mx[2] = fmaxf(a, b);
        a = run_eval<3>(r3, j0); b = run_eval<3>(r3, j0 + 31);
        mn[3] = fminf(a, b); mx[3] = fmaxf(a, b);
        a = run_eval<4>(r4, j0); b = run_eval<4>(r4, j0 + 31);
        mn[4] = fminf(a, b); mx[4] = fmaxf(a, b);
    }
    if (wrap) {   // P1 wraps to 0 at j=1023: also sample j=1022
        float c;
        c = run_eval<0>(r0, 1022); mn[0] = fminf(mn[0], c); mx[0] = fmaxf(mx[0], c);
        c = run_eval<1>(r1, 1022); mn[1] = fminf(mn[1], c); mx[1] = fmaxf(mx[1], c);
        c = run_eval<2>(r2, 1022); mn[2] = fminf(mn[2], c); mx[2] = fmaxf(mx[2], c);
        c = run_eval<3>(r3, 1022); mn[3] = fminf(mn[3], c); mx[3] = fmaxf(mx[3], c);
        c = run_eval<4>(r4, 1022); mn[4] = fminf(mn[4], c); mx[4] = fmaxf(mx[4], c);
    }

#pragma unroll
    for (int o = 0; o < 5; o++) {
#pragma unroll
        for (int d = 16; d > 0; d >>= 1) {
            mn[o] = fminf(mn[o], __shfl_xor_sync(0xFFFFFFFFu, mn[o], d));
            mx[o] = fmaxf(mx[o], __shfl_xor_sync(0xFFFFFFFFu, mx[o], d));
        }
    }
    __shared__ float smn[5][8], smx[5][8];
    int w = threadIdx.x >> 5, lane = threadIdx.x & 31;
    if (lane == 0) {
#pragma unroll
        for (int o = 0; o < 5; o++) { smn[o][w] = mn[o]; smx[o][w] = mx[o]; }
    }
    __syncthreads();
    if (threadIdx.x < 5) {
        int o = threadIdx.x;
        float a = smn[o][0], b = smx[o][0];
#pragma unroll
        for (int k = 1; k < 8; k++) { a = fminf(a, smn[o][k]); b = fmaxf(b, smx[o][k]); }
        g_bmn[o][blockIdx.x] = a;
        g_bmx[o][blockIdx.x] = b;
    }
}

// ---------------------------------------------------------------------------
// K2 k_noise (PDL-dependent on k_minmax): prologue (fill + run_consts +
// unscaled incremental init) runs BEFORE the wait, overlapping k_minmax.
// After wait: reduce 128 partials, fold normalization, write noise * mix.
// launch_dependents at entry lets k_apply start prefetching image.
// ---------------------------------------------------------------------------
__global__ void __launch_bounds__(256) k_noise(
    const float* __restrict__ a0, const float* __restrict__ a1,
    const float* __restrict__ a2, const float* __restrict__ a3,
    const float* __restrict__ a4, const float* __restrict__ mixp)
{
    asm volatile("griddepcontrol.launch_dependents;");

    __shared__ float2 sgrad[NGRAD_SM];
    __shared__ float smn[5][8], smx[5][8];
    __shared__ float fmn[5], fmx[5];

    int i0 = blockIdx.x * 2;
    fill_grad_sm(sgrad, i0, a0, a1, a2, a3, a4);
    __syncthreads();

    int t = blockIdx.x * 256 + threadIdx.x;   // 0..131071
    int i  = t >> 7;
    int j0 = (t & 127) << 3;
    bool wrap = (j0 == 1016);

    RunConst r0 = run_const_sm<0>(sgrad, i, j0);
    RunConst r1 = run_const_sm<1>(sgrad, i, j0);
    RunConst r2 = run_const_sm<2>(sgrad, i, j0);
    RunConst r3 = run_const_sm<3>(sgrad, i, j0);
    RunConst r4 = run_const_sm<4>(sgrad, i, j0);

    // unscaled incremental state (independent of min/max):
    //   t0_o(j) = C0 + P1*D0;  T1u_o(j) = E + P1*F;  step by dl per pixel
    const float dl[5] = {4.0f / 1023.0f, 8.0f / 1023.0f, 16.0f / 1023.0f,
                         32.0f / 1023.0f, 64.0f / 1023.0f};
    float P1[5], t0[5], dt0[5], T1u[5], dT1u[5];
#define INITO(o, rc)                                                    \
    {                                                                   \
        float vx = (float)j0 * dl[o];                                   \
        P1[o]   = vx - floorf(vx);                                      \
        t0[o]   = fmaf(P1[o], rc.D0, rc.C0);                            \
        dt0[o]  = dl[o] * rc.D0;                                        \
        T1u[o]  = fmaf(P1[o], rc.F, rc.E);                              \
        dT1u[o] = dl[o] * rc.F;                                         \
    }
    INITO(0, r0) INITO(1, r1) INITO(2, r2) INITO(3, r3) INITO(4, r4)
#undef INITO

    // ---- wait for k_minmax grid to fully complete --------------------------
    asm volatile("griddepcontrol.wait;" ::: "memory");

    // reduce the 128 partials (every thread loads idx&127; dups are harmless)
    int w = threadIdx.x >> 5, lane = threadIdx.x & 31;
    {
        int pi = threadIdx.x & (MNBLK - 1);
        float pm[5], px[5];
#pragma unroll
        for (int o = 0; o < 5; o++) {
            pm[o] = __ldcg(&g_bmn[o][pi]);
            px[o] = __ldcg(&g_bmx[o][pi]);
        }
#pragma unroll
        for (int o = 0; o < 5; o++) {
#pragma unroll
            for (int d = 16; d > 0; d >>= 1) {
                pm[o] = fminf(pm[o], __shfl_xor_sync(0xFFFFFFFFu, pm[o], d));
                px[o] = fmaxf(px[o], __shfl_xor_sync(0xFFFFFFFFu, px[o], d));
            }
        }
        if (lane == 0) {
#pragma unroll
            for (int o = 0; o < 5; o++) { smn[o][w] = pm[o]; smx[o][w] = px[o]; }
        }
    }
    __syncthreads();
    if (threadIdx.x < 5) {
        int o = threadIdx.x;
        float a = smn[o][0], b = smx[o][0];
#pragma unroll
        for (int k = 1; k < 8; k++) { a = fminf(a, smn[o][k]); b = fmaxf(b, smx[o][k]); }
        fmn[o] = a; fmx[o] = b;
    }
    __syncthreads();

    // fold normalization into per-octave scale + shared bias
    float mixv = *mixp;
    const float amps[5] = {0.1f, 0.05f, 0.025f, 0.0125f, 0.00625f};
    float s[5], B = 0.0f;
#pragma unroll
    for (int o = 0; o < 5; o++) {
        float mnv = fmn[o], mxv = fmx[o];
        float inv = 1.0f / (mxv - mnv);
        float am = amps[o] * mixv;
        s[o] = 2.0f * am * inv;
        B += am * (-2.0f * mnv * inv - 1.0f);
    }

    float vals[8];
#pragma unroll
    for (int k = 0; k < 8; k++) {
        float acc = B;
#pragma unroll
        for (int o = 0; o < 5; o++) {
            float u = P1[o] * P1[o];
            float v = fmaf(-2.0f, P1[o], 3.0f);
            acc = fmaf(s[o], fmaf(u * v, T1u[o], t0[o]), acc);
        }
        vals[k] = acc;
#pragma unroll
        for (int o = 0; o < 5; o++) {
            P1[o] += dl[o]; t0[o] += dt0[o]; T1u[o] += dT1u[o];
        }
    }
    if (wrap) {   // j=1023: P1 wraps to 0 at every octave -> n_o = C0_o
        float acc = B;
        acc = fmaf(s[0], r0.C0, acc);
        acc = fmaf(s[1], r1.C0, acc);
        acc = fmaf(s[2], r2.C0, acc);
        acc = fmaf(s[3], r3.C0, acc);
        acc = fmaf(s[4], r4.C0, acc);
        vals[7] = acc;
    }

    int p4 = t << 1;
    g_noise4[p4]     = make_float4(vals[0], vals[1], vals[2], vals[3]);
    g_noise4[p4 + 1] = make_float4(vals[4], vals[5], vals[6], vals[7]);
}

// ---------------------------------------------------------------------------
// K3 k_apply (PDL-dependent on k_noise): HBM-bound streaming apply.
// Proven VPT=4 shape: img loads issued BEFORE griddepcontrol.wait;
// noise reads/stores after the wait.
// ---------------------------------------------------------------------------
#define VPT 4
__global__ void __launch_bounds__(256) k_apply(const float4* __restrict__ img,
                                               float4* __restrict__ out, int n4) {
    int base = blockIdx.x * (256 * VPT) + threadIdx.x;

    if (base + 3 * 256 < n4) {
        float4 v0 = __ldcs(img + base);
        float4 v1 = __ldcs(img + base + 256);
        float4 v2 = __ldcs(img + base + 512);
        float4 v3 = __ldcs(img + base + 768);

        asm volatile("griddepcontrol.wait;" ::: "memory");

        float4 n0 = g_noise4[(base)       & (NPIX4 - 1)];
        float4 n1 = g_noise4[(base + 256) & (NPIX4 - 1)];
        float4 n2 = g_noise4[(base + 512) & (NPIX4 - 1)];
        float4 n3 = g_noise4[(base + 768) & (NPIX4 - 1)];

        v0.x = fminf(fmaxf(v0.x + n0.x, 0.0f), 1.0f);
        v0.y = fminf(fmaxf(v0.y + n0.y, 0.0f), 1.0f);
        v0.z = fminf(fmaxf(v0.z + n0.z, 0.0f), 1.0f);
        v0.w = fminf(fmaxf(v0.w + n0.w, 0.0f), 1.0f);
        v1.x = fminf(fmaxf(v1.x + n1.x, 0.0f), 1.0f);
        v1.y = fminf(fmaxf(v1.y + n1.y, 0.0f), 1.0f);
        v1.z = fminf(fmaxf(v1.z + n1.z, 0.0f), 1.0f);
        v1.w = fminf(fmaxf(v1.w + n1.w, 0.0f), 1.0f);
        v2.x = fminf(fmaxf(v2.x + n2.x, 0.0f), 1.0f);
        v2.y = fminf(fmaxf(v2.y + n2.y, 0.0f), 1.0f);
        v2.z = fminf(fmaxf(v2.z + n2.z, 0.0f), 1.0f);
        v2.w = fminf(fmaxf(v2.w + n2.w, 0.0f), 1.0f);
        v3.x = fminf(fmaxf(v3.x + n3.x, 0.0f), 1.0f);
        v3.y = fminf(fmaxf(v3.y + n3.y, 0.0f), 1.0f);
        v3.z = fminf(fmaxf(v3.z + n3.z, 0.0f), 1.0f);
        v3.w = fminf(fmaxf(v3.w + n3.w, 0.0f), 1.0f);

        __stcs(out + base,       v0);
        __stcs(out + base + 256, v1);
        __stcs(out + base + 512, v2);
        __stcs(out + base + 768, v3);
    } else {
        asm volatile("griddepcontrol.wait;" ::: "memory");
        for (int k = 0; k < VPT; k++) {
            int idx = base + k * 256;
            if (idx >= n4) break;
            float4 nz = g_noise4[idx & (NPIX4 - 1)];
            float4 v = __ldcs(img + idx);
            v.x = fminf(fmaxf(v.x + nz.x, 0.0f), 1.0f);
            v.y = fminf(fmaxf(v.y + nz.y, 0.0f), 1.0f);
            v.z = fminf(fmaxf(v.z + nz.z, 0.0f), 1.0f);
            v.w = fminf(fmaxf(v.w + nz.w, 0.0f), 1.0f);
            __stcs(out + idx, v);
        }
    }
}

// ---------------------------------------------------------------------------
extern "C" void kernel_launch(void* const* d_in, const int* in_sizes, int n_in,
                              void* d_out, int out_size) {
    const float* image = nullptr;
    const float* mixp  = nullptr;
    const float* ang[5] = {nullptr, nullptr, nullptr, nullptr, nullptr};

    for (int k = 0; k < n_in; k++) {
        int s = in_sizes[k];
        const float* p = (const float*)d_in[k];
        if      (s == 1)    mixp   = p;
        else if (s == 25)   ang[0] = p;
        else if (s == 81)   ang[1] = p;
        else if (s == 289)  ang[2] = p;
        else if (s == 1089) ang[3] = p;
        else if (s == 4225) ang[4] = p;
        else                image  = p;   // 16*3*1024*1024
    }

    int n4 = out_size / 4;
    unsigned ablocks = (unsigned)((n4 + 256 * VPT - 1) / (256 * VPT));

    // K1: plain launch (128 blocks)
    k_minmax<<<MNBLK, 256>>>(ang[0], ang[1], ang[2], ang[3], ang[4]);

    // K2: PDL-dependent launch (prologue overlaps k_minmax)
    cudaLaunchAttribute attrs[1];
    attrs[0].id = cudaLaunchAttributeProgrammaticStreamSerialization;
    attrs[0].val.programmaticStreamSerializationAllowed = 1;

    cudaLaunchConfig_t cfg2 = {};
    cfg2.gridDim  = dim3(SBLK, 1, 1);
    cfg2.blockDim = dim3(256, 1, 1);
    cfg2.attrs = attrs;
    cfg2.numAttrs = 1;
    cudaError_t e2 = cudaLaunchKernelEx(&cfg2, k_noise,
                                        ang[0], ang[1], ang[2], ang[3], ang[4], mixp);
    if (e2 != cudaSuccess) {
        k_noise<<<SBLK, 256>>>(ang[0], ang[1], ang[2], ang[3], ang[4], mixp);
    }

    // K3: PDL-dependent launch (img prefetch overlaps k_noise)
    cudaLaunchConfig_t cfg3 = {};
    cfg3.gridDim  = dim3(ablocks, 1, 1);
    cfg3.blockDim = dim3(256, 1, 1);
    cfg3.attrs = attrs;
    cfg3.numAttrs = 1;
    cudaError_t e3 = cudaLaunchKernelEx(&cfg3, k_apply,
                                        (const float4*)image, (float4*)d_out, n4);
    if (e3 != cudaSuccess) {
        k_apply<<<ablocks, 256>>>((const float4*)image, (float4*)d_out, n4);
    }
}